// round 12
// baseline (speedup 1.0000x reference)
#include <cuda_runtime.h>

// PixelWiseRNN: h_t = tanh(w_ih*x_t + b_ih + w_hh*h_{t-1} + b_hh), h_0 = 0
// x: (B, T, Z, H, W) fp32, params: (Z, H, W) fp32, out: (B, T, Z, H, W) fp32
// B=4, T=256, Z=16, H=64, W=64  ->  P = Z*H*W = 65536 pixels per batch.
//
// R11: R4 chassis (best BENCH kernel: unroll-4, single xv rotation, MUFU.TANH,
// 262144 threads @ 256/block) + streaming cache hints as the single new
// variable. x and out have zero reuse; __ldcs/__stcs (evict-first) reduce L2
// thrash between the read stream and the previous replay's dirty writebacks
// in the graph-replay steady state (which is what the bench times, unlike
// ncu's cache-flushed single shot).

#define RNN_B 4
#define RNN_T 256
#define RNN_P 65536   // Z*H*W

__device__ __forceinline__ float hw_tanh(float z)
{
    float r;
    asm("tanh.approx.f32 %0, %1;" : "=f"(r) : "f"(z));
    return r;
}

__global__ __launch_bounds__(256) void pixel_rnn_kernel(
    const float* __restrict__ x,
    const float* __restrict__ w_ih,
    const float* __restrict__ w_hh,
    const float* __restrict__ b_ih,
    const float* __restrict__ b_hh,
    float* __restrict__ out)
{
    const int gid = blockIdx.x * blockDim.x + threadIdx.x;   // [0, B*P)
    const int b = gid >> 16;          // gid / P
    const int p = gid & (RNN_P - 1);  // gid % P

    const float wi   = w_ih[p];
    const float wh   = w_hh[p];
    const float bias = b_ih[p] + b_hh[p];

    const size_t base = (size_t)b * RNN_T * RNN_P + p;
    const float* __restrict__ xp = x + base;
    float* __restrict__ op = out + base;

    float h  = 0.0f;
    float xv = __ldcs(xp);   // prefetched x_0

    #pragma unroll 4
    for (int t = 0; t < RNN_T; t++) {
        // Prefetch next x off the dependency chain (clamped at the end).
        const int tn = (t + 1 < RNN_T) ? (t + 1) : t;
        const float xn = __ldcs(xp + (size_t)tn * RNN_P);

        // Off-chain part first: a = wi*x + bias (independent of h).
        const float a = fmaf(wi, xv, bias);
        h = hw_tanh(fmaf(wh, h, a));

        __stcs(op + (size_t)t * RNN_P, h);
        xv = xn;
    }
}

extern "C" void kernel_launch(void* const* d_in, const int* in_sizes, int n_in,
                              void* d_out, int out_size)
{
    const float* x    = (const float*)d_in[0];
    const float* w_ih = (const float*)d_in[1];
    const float* w_hh = (const float*)d_in[2];
    const float* b_ih = (const float*)d_in[3];
    const float* b_hh = (const float*)d_in[4];
    float* out = (float*)d_out;

    const int total_threads = RNN_B * RNN_P;   // 262144
    const int block = 256;
    const int grid = total_threads / block;    // 1024

    pixel_rnn_kernel<<<grid, block>>>(x, w_ih, w_hh, b_ih, b_hh, out);
}

// round 13
// speedup vs baseline: 1.1779x; 1.1779x over previous
#include <cuda_runtime.h>

// PixelWiseRNN: h_t = tanh(w_ih*x_t + b_ih + w_hh*h_{t-1} + b_hh), h_0 = 0
// x: (B, T, Z, H, W) fp32, params: (Z, H, W) fp32, out: (B, T, Z, H, W) fp32
// B=4, T=256, Z=16, H=64, W=64  ->  P = Z*H*W = 65536 pixels per batch.
//
// R12: R4 chassis verbatim (best bench kernel: unroll-4, single xv rotation,
// MUFU.TANH, default cache policy — .cs confirmed harmful in R11). Single
// variable: block size 256 -> 128. 2048 CTAs smooths the 148-SM wave balance
// and halves the per-CTA synchronized LDG burst into the L1tex queue,
// attacking the steady-state tail spread that separates bench from ncu time.

#define RNN_B 4
#define RNN_T 256
#define RNN_P 65536   // Z*H*W

__device__ __forceinline__ float hw_tanh(float z)
{
    float r;
    asm("tanh.approx.f32 %0, %1;" : "=f"(r) : "f"(z));
    return r;
}

__global__ __launch_bounds__(128) void pixel_rnn_kernel(
    const float* __restrict__ x,
    const float* __restrict__ w_ih,
    const float* __restrict__ w_hh,
    const float* __restrict__ b_ih,
    const float* __restrict__ b_hh,
    float* __restrict__ out)
{
    const int gid = blockIdx.x * blockDim.x + threadIdx.x;   // [0, B*P)
    const int b = gid >> 16;          // gid / P
    const int p = gid & (RNN_P - 1);  // gid % P

    const float wi   = w_ih[p];
    const float wh   = w_hh[p];
    const float bias = b_ih[p] + b_hh[p];

    const size_t base = (size_t)b * RNN_T * RNN_P + p;
    const float* __restrict__ xp = x + base;
    float* __restrict__ op = out + base;

    float h  = 0.0f;
    float xv = xp[0];   // prefetched x_0

    #pragma unroll 4
    for (int t = 0; t < RNN_T; t++) {
        // Prefetch next x off the dependency chain (clamped at the end).
        const int tn = (t + 1 < RNN_T) ? (t + 1) : t;
        const float xn = xp[(size_t)tn * RNN_P];

        // Off-chain part first: a = wi*x + bias (independent of h).
        const float a = fmaf(wi, xv, bias);
        h = hw_tanh(fmaf(wh, h, a));

        op[(size_t)t * RNN_P] = h;
        xv = xn;
    }
}

extern "C" void kernel_launch(void* const* d_in, const int* in_sizes, int n_in,
                              void* d_out, int out_size)
{
    const float* x    = (const float*)d_in[0];
    const float* w_ih = (const float*)d_in[1];
    const float* w_hh = (const float*)d_in[2];
    const float* b_ih = (const float*)d_in[3];
    const float* b_hh = (const float*)d_in[4];
    float* out = (float*)d_out;

    const int total_threads = RNN_B * RNN_P;   // 262144
    const int block = 128;
    const int grid = total_threads / block;    // 2048

    pixel_rnn_kernel<<<grid, block>>>(x, w_ih, w_hh, b_ih, b_hh, out);
}

// round 14
// speedup vs baseline: 1.1914x; 1.0114x over previous
#include <cuda_runtime.h>

// PixelWiseRNN: h_t = tanh(w_ih*x_t + b_ih + w_hh*h_{t-1} + b_hh), h_0 = 0
// x: (B, T, Z, H, W) fp32, params: (Z, H, W) fp32, out: (B, T, Z, H, W) fp32
// B=4, T=256, Z=16, H=64, W=64  ->  P = Z*H*W = 65536 pixels per batch.
//
// R13: attack the LSU-issue co-limiter (~65% occupied with scalar LDG/STG:
// STG.32 ~5cyc, LDG ~1.8cyc -> ~97K of ~150K SM-cycles). float2 halves
// LSU ops per byte (LDG.64/STG.64). Unlike R1's float4 (occ collapsed to
// 20%), float2 keeps 131072 threads -> ~27 warps/SM x 2 independent tanh
// chains = same ~55 chain contexts/SM as the scalar kernel. Chassis
// otherwise = R12 winner: 128-thread blocks, unroll-4 single-rotation body,
// MUFU.TANH, default cache policy.

#define RNN_B  4
#define RNN_T  256
#define RNN_P  65536          // Z*H*W
#define RNN_NV (RNN_P / 2)    // 32768 float2 vectors per batch slice

__device__ __forceinline__ float hw_tanh(float z)
{
    float r;
    asm("tanh.approx.f32 %0, %1;" : "=f"(r) : "f"(z));
    return r;
}

__global__ __launch_bounds__(128) void pixel_rnn_kernel(
    const float* __restrict__ x,
    const float* __restrict__ w_ih,
    const float* __restrict__ w_hh,
    const float* __restrict__ b_ih,
    const float* __restrict__ b_hh,
    float* __restrict__ out)
{
    const int gid = blockIdx.x * blockDim.x + threadIdx.x;  // [0, B*NV) = 131072
    const int b = gid >> 15;            // gid / NV
    const int v = gid & (RNN_NV - 1);   // gid % NV
    const int p = v << 1;               // first of 2 adjacent pixels

    const float2 wi = *(const float2*)(w_ih + p);
    const float2 wh = *(const float2*)(w_hh + p);
    const float2 bi = *(const float2*)(b_ih + p);
    const float2 bh = *(const float2*)(b_hh + p);
    const float2 bias = make_float2(bi.x + bh.x, bi.y + bh.y);

    const size_t base = (size_t)b * RNN_T * RNN_P + p;
    const float2* __restrict__ xp = (const float2*)(x + base);
    float2* __restrict__ op = (float2*)(out + base);
    const int stride = RNN_P / 2;       // per-timestep stride in float2 units

    float2 h  = make_float2(0.f, 0.f);
    float2 xv = xp[0];   // prefetched x_0

    #pragma unroll 4
    for (int t = 0; t < RNN_T; t++) {
        // Prefetch next x off the dependency chain (clamped at the end).
        const int tn = (t + 1 < RNN_T) ? (t + 1) : t;
        const float2 xn = xp[(size_t)tn * stride];

        // Off-chain: a = wi*x + bias (independent of h). Two independent
        // chains (.x/.y) interleave through the FMA/MUFU pipes.
        const float ax = fmaf(wi.x, xv.x, bias.x);
        const float ay = fmaf(wi.y, xv.y, bias.y);
        h.x = hw_tanh(fmaf(wh.x, h.x, ax));
        h.y = hw_tanh(fmaf(wh.y, h.y, ay));

        op[(size_t)t * stride] = h;
        xv = xn;
    }
}

extern "C" void kernel_launch(void* const* d_in, const int* in_sizes, int n_in,
                              void* d_out, int out_size)
{
    const float* x    = (const float*)d_in[0];
    const float* w_ih = (const float*)d_in[1];
    const float* w_hh = (const float*)d_in[2];
    const float* b_ih = (const float*)d_in[3];
    const float* b_hh = (const float*)d_in[4];
    float* out = (float*)d_out;

    const int total_threads = RNN_B * RNN_NV;  // 131072
    const int block = 128;
    const int grid = total_threads / block;    // 1024

    pixel_rnn_kernel<<<grid, block>>>(x, w_ih, w_hh, b_ih, b_hh, out);
}

// round 15
// speedup vs baseline: 1.2283x; 1.0310x over previous
#include <cuda_runtime.h>

// PixelWiseRNN: h_t = tanh(w_ih*x_t + b_ih + w_hh*h_{t-1} + b_hh), h_0 = 0
// x: (B, T, Z, H, W) fp32, params: (Z, H, W) fp32, out: (B, T, Z, H, W) fp32
// B=4, T=256, Z=16, H=64, W=64  ->  P = Z*H*W = 65536 pixels per batch.
//
// R14: R13 float2 chassis (best bench: LDG.64/STG.64, 131072 threads,
// 128/block, MUFU.TANH, single xv rotation) with unroll 4 -> 8. Doubles
// per-warp bytes in flight (2 KB) while per-SM front-batch queue depth
// (27.7 warps x 8 = 222) stays half of the R5/R7 scalar-8 shape (443) that
// inflated steady-state bench time.

#define RNN_B  4
#define RNN_T  256
#define RNN_P  65536          // Z*H*W
#define RNN_NV (RNN_P / 2)    // 32768 float2 vectors per batch slice

__device__ __forceinline__ float hw_tanh(float z)
{
    float r;
    asm("tanh.approx.f32 %0, %1;" : "=f"(r) : "f"(z));
    return r;
}

__global__ __launch_bounds__(128) void pixel_rnn_kernel(
    const float* __restrict__ x,
    const float* __restrict__ w_ih,
    const float* __restrict__ w_hh,
    const float* __restrict__ b_ih,
    const float* __restrict__ b_hh,
    float* __restrict__ out)
{
    const int gid = blockIdx.x * blockDim.x + threadIdx.x;  // [0, B*NV) = 131072
    const int b = gid >> 15;            // gid / NV
    const int v = gid & (RNN_NV - 1);   // gid % NV
    const int p = v << 1;               // first of 2 adjacent pixels

    const float2 wi = *(const float2*)(w_ih + p);
    const float2 wh = *(const float2*)(w_hh + p);
    const float2 bi = *(const float2*)(b_ih + p);
    const float2 bh = *(const float2*)(b_hh + p);
    const float2 bias = make_float2(bi.x + bh.x, bi.y + bh.y);

    const size_t base = (size_t)b * RNN_T * RNN_P + p;
    const float2* __restrict__ xp = (const float2*)(x + base);
    float2* __restrict__ op = (float2*)(out + base);
    const int stride = RNN_P / 2;       // per-timestep stride in float2 units

    float2 h  = make_float2(0.f, 0.f);
    float2 xv = xp[0];   // prefetched x_0

    #pragma unroll 8
    for (int t = 0; t < RNN_T; t++) {
        // Prefetch next x off the dependency chain (clamped at the end).
        const int tn = (t + 1 < RNN_T) ? (t + 1) : t;
        const float2 xn = xp[(size_t)tn * stride];

        // Off-chain: a = wi*x + bias (independent of h). Two independent
        // chains (.x/.y) interleave through the FMA/MUFU pipes.
        const float ax = fmaf(wi.x, xv.x, bias.x);
        const float ay = fmaf(wi.y, xv.y, bias.y);
        h.x = hw_tanh(fmaf(wh.x, h.x, ax));
        h.y = hw_tanh(fmaf(wh.y, h.y, ay));

        op[(size_t)t * stride] = h;
        xv = xn;
    }
}

extern "C" void kernel_launch(void* const* d_in, const int* in_sizes, int n_in,
                              void* d_out, int out_size)
{
    const float* x    = (const float*)d_in[0];
    const float* w_ih = (const float*)d_in[1];
    const float* w_hh = (const float*)d_in[2];
    const float* b_ih = (const float*)d_in[3];
    const float* b_hh = (const float*)d_in[4];
    float* out = (float*)d_out;

    const int total_threads = RNN_B * RNN_NV;  // 131072
    const int block = 128;
    const int grid = total_threads / block;    // 1024

    pixel_rnn_kernel<<<grid, block>>>(x, w_ih, w_hh, b_ih, b_hh, out);
}

// round 16
// speedup vs baseline: 1.2361x; 1.0063x over previous
#include <cuda_runtime.h>

// PixelWiseRNN: h_t = tanh(w_ih*x_t + b_ih + w_hh*h_{t-1} + b_hh), h_0 = 0
// x: (B, T, Z, H, W) fp32, params: (Z, H, W) fp32, out: (B, T, Z, H, W) fp32
// B=4, T=256, Z=16, H=64, W=64  ->  P = Z*H*W = 65536 pixels per batch.
//
// R15: R14 chassis (float2, 131072 threads, 128/block, MUFU.TANH, single xv
// rotation) with unroll 8 -> 16. Continues the winning axis: deeper per-warp
// load batches (4 KB in flight) at moderate warp count, smoothing the DRAM
// duty cycle. Single-variable change; revert to R14 if the steady-state
// bench gap inflates.

#define RNN_B  4
#define RNN_T  256
#define RNN_P  65536          // Z*H*W
#define RNN_NV (RNN_P / 2)    // 32768 float2 vectors per batch slice

__device__ __forceinline__ float hw_tanh(float z)
{
    float r;
    asm("tanh.approx.f32 %0, %1;" : "=f"(r) : "f"(z));
    return r;
}

__global__ __launch_bounds__(128) void pixel_rnn_kernel(
    const float* __restrict__ x,
    const float* __restrict__ w_ih,
    const float* __restrict__ w_hh,
    const float* __restrict__ b_ih,
    const float* __restrict__ b_hh,
    float* __restrict__ out)
{
    const int gid = blockIdx.x * blockDim.x + threadIdx.x;  // [0, B*NV) = 131072
    const int b = gid >> 15;            // gid / NV
    const int v = gid & (RNN_NV - 1);   // gid % NV
    const int p = v << 1;               // first of 2 adjacent pixels

    const float2 wi = *(const float2*)(w_ih + p);
    const float2 wh = *(const float2*)(w_hh + p);
    const float2 bi = *(const float2*)(b_ih + p);
    const float2 bh = *(const float2*)(b_hh + p);
    const float2 bias = make_float2(bi.x + bh.x, bi.y + bh.y);

    const size_t base = (size_t)b * RNN_T * RNN_P + p;
    const float2* __restrict__ xp = (const float2*)(x + base);
    float2* __restrict__ op = (float2*)(out + base);
    const int stride = RNN_P / 2;       // per-timestep stride in float2 units

    float2 h  = make_float2(0.f, 0.f);
    float2 xv = xp[0];   // prefetched x_0

    #pragma unroll 16
    for (int t = 0; t < RNN_T; t++) {
        // Prefetch next x off the dependency chain (clamped at the end).
        const int tn = (t + 1 < RNN_T) ? (t + 1) : t;
        const float2 xn = xp[(size_t)tn * stride];

        // Off-chain: a = wi*x + bias (independent of h). Two independent
        // chains (.x/.y) interleave through the FMA/MUFU pipes.
        const float ax = fmaf(wi.x, xv.x, bias.x);
        const float ay = fmaf(wi.y, xv.y, bias.y);
        h.x = hw_tanh(fmaf(wh.x, h.x, ax));
        h.y = hw_tanh(fmaf(wh.y, h.y, ay));

        op[(size_t)t * stride] = h;
        xv = xn;
    }
}

extern "C" void kernel_launch(void* const* d_in, const int* in_sizes, int n_in,
                              void* d_out, int out_size)
{
    const float* x    = (const float*)d_in[0];
    const float* w_ih = (const float*)d_in[1];
    const float* w_hh = (const float*)d_in[2];
    const float* b_ih = (const float*)d_in[3];
    const float* b_hh = (const float*)d_in[4];
    float* out = (float*)d_out;

    const int total_threads = RNN_B * RNN_NV;  // 131072
    const int block = 128;
    const int grid = total_threads / block;    // 1024

    pixel_rnn_kernel<<<grid, block>>>(x, w_ih, w_hh, b_ih, b_hh, out);
}